// round 12
// baseline (speedup 1.0000x reference)
#include <cuda_runtime.h>

#define N_NODES 50000
#define HYPER_DIM 128
#define NNZ 800000
#define LEAKY 0.2f
#define LN_EPS 1e-5f
#define FULL 0xFFFFFFFFu

#define CAP 64                        // bucket capacity (max degree ~35, 12-sigma safe)
#define E4GRID ((NNZ / 4 + 255) / 256)
#define NPAIRS (N_NODES / 2)          // 25000 warps, 2 nodes each
#define PGRID ((NPAIRS * 32 + 255) / 256)   // 3125 blocks

// ---------------------------------------------------------------------------
// Scratch (allocation-free __device__ globals).
// g_cntA/g_cntB are zero at module load; the LAST SpMM of every call
// re-zeroes them, so each kernel_launch invocation starts clean.
// ---------------------------------------------------------------------------
__device__ int g_cntA[N_NODES];
__device__ int g_cntB[N_NODES];
__device__ int2 g_edgeA[(size_t)N_NODES * CAP];  // bucketed by col: {row, val}
__device__ int2 g_edgeB[(size_t)N_NODES * CAP];  // bucketed by row: {col, val}
__device__ float g_ht[(size_t)N_NODES * HYPER_DIM];
__device__ float g_embs[(size_t)N_NODES * HYPER_DIM];

// ---------------------------------------------------------------------------
// 1. scatter into fixed-cap buckets, both orientations, 4 edges/thread.
// ---------------------------------------------------------------------------
__global__ void scatter_kernel(const int4* __restrict__ rows4,
                               const int4* __restrict__ cols4,
                               const float4* __restrict__ vals4) {
    int i = blockIdx.x * blockDim.x + threadIdx.x;
    if (i >= NNZ / 4) return;
    int4 r = rows4[i];
    int4 c = cols4[i];
    float4 v = vals4[i];

    int p0 = atomicAdd(&g_cntA[c.x], 1);
    int p1 = atomicAdd(&g_cntA[c.y], 1);
    int p2 = atomicAdd(&g_cntA[c.z], 1);
    int p3 = atomicAdd(&g_cntA[c.w], 1);
    g_edgeA[(size_t)c.x * CAP + p0] = make_int2(r.x, __float_as_int(v.x));
    g_edgeA[(size_t)c.y * CAP + p1] = make_int2(r.y, __float_as_int(v.y));
    g_edgeA[(size_t)c.z * CAP + p2] = make_int2(r.z, __float_as_int(v.z));
    g_edgeA[(size_t)c.w * CAP + p3] = make_int2(r.w, __float_as_int(v.w));

    int q0 = atomicAdd(&g_cntB[r.x], 1);
    int q1 = atomicAdd(&g_cntB[r.y], 1);
    int q2 = atomicAdd(&g_cntB[r.z], 1);
    int q3 = atomicAdd(&g_cntB[r.w], 1);
    g_edgeB[(size_t)r.x * CAP + q0] = make_int2(c.x, __float_as_int(v.x));
    g_edgeB[(size_t)r.y * CAP + q1] = make_int2(c.y, __float_as_int(v.y));
    g_edgeB[(size_t)r.z * CAP + q2] = make_int2(c.z, __float_as_int(v.z));
    g_edgeB[(size_t)r.w * CAP + q3] = make_int2(c.w, __float_as_int(v.w));
}

// ---------------------------------------------------------------------------
// 2. gather SpMM, TWO nodes per warp (2x MLP for latency hiding).
//    fp32 accumulate; optional fused leaky + LayerNorm + residual.
// ---------------------------------------------------------------------------
template <int FUSE_LN, int DO_LEAKY>
__device__ __forceinline__ float4 ln_epilogue(float4 acc, int n, int lane,
                                              const float* __restrict__ gamma,
                                              const float* __restrict__ beta,
                                              const float* __restrict__ res) {
    if (DO_LEAKY) {
        acc.x = acc.x >= 0.f ? acc.x : LEAKY * acc.x;
        acc.y = acc.y >= 0.f ? acc.y : LEAKY * acc.y;
        acc.z = acc.z >= 0.f ? acc.z : LEAKY * acc.z;
        acc.w = acc.w >= 0.f ? acc.w : LEAKY * acc.w;
    }
    float s = acc.x + acc.y + acc.z + acc.w;
    #pragma unroll
    for (int m = 16; m > 0; m >>= 1) s += __shfl_xor_sync(FULL, s, m);
    float mu = s * (1.f / HYPER_DIM);

    float dx = acc.x - mu, dy = acc.y - mu, dz = acc.z - mu, dw = acc.w - mu;
    float sq = dx * dx + dy * dy + dz * dz + dw * dw;
    #pragma unroll
    for (int m = 16; m > 0; m >>= 1) sq += __shfl_xor_sync(FULL, sq, m);
    float rstd = rsqrtf(sq * (1.f / HYPER_DIM) + LN_EPS);

    float4 g = reinterpret_cast<const float4*>(gamma)[lane];
    float4 b = reinterpret_cast<const float4*>(beta)[lane];
    float4 r = reinterpret_cast<const float4*>(res + (size_t)n * HYPER_DIM)[lane];

    float4 o;
    o.x = dx * rstd * g.x + b.x + r.x;
    o.y = dy * rstd * g.y + b.y + r.y;
    o.z = dz * rstd * g.z + b.z + r.z;
    o.w = dw * rstd * g.w + b.w + r.w;
    return o;
}

template <int FUSE_LN, int DO_LEAKY, int ZERO_CNT>
__global__ void gather_spmm2_kernel(const int* __restrict__ cnt,
                                    const int2* __restrict__ edge,
                                    const float* __restrict__ x,
                                    const float* __restrict__ gamma,
                                    const float* __restrict__ beta,
                                    const float* __restrict__ res,
                                    float* __restrict__ out) {
    int w = (blockIdx.x * blockDim.x + threadIdx.x) >> 5;
    if (w >= NPAIRS) return;
    int lane = threadIdx.x & 31;
    int n0 = w * 2;
    int n1 = n0 + 1;            // N_NODES even -> always valid

    int deg0 = cnt[n0];
    int deg1 = cnt[n1];
    const int2* b0 = edge + (size_t)n0 * CAP;
    const int2* b1 = edge + (size_t)n1 * CAP;

    if (ZERO_CNT) {             // retire counters for next launch (last kernel)
        if (lane < 2) g_cntA[n0 + lane] = 0;
        else if (lane < 4) g_cntB[n0 + lane - 2] = 0;
    }

    const float4* xr = reinterpret_cast<const float4*>(x);
    float4 acc0 = make_float4(0.f, 0.f, 0.f, 0.f);
    float4 acc1 = make_float4(0.f, 0.f, 0.f, 0.f);

    #pragma unroll
    for (int base = 0; base < CAP; base += 32) {
        int m0 = min(32, max(0, deg0 - base));
        int m1 = min(32, max(0, deg1 - base));
        if ((m0 | m1) == 0) break;
        int2 ev0 = (lane < m0) ? b0[base + lane] : make_int2(0, 0);
        int2 ev1 = (lane < m1) ? b1[base + lane] : make_int2(0, 0);
        int mm = max(m0, m1);
        #pragma unroll 4
        for (int t = 0; t < mm; t++) {
            int j0   = __shfl_sync(FULL, ev0.x, t);
            float v0 = __int_as_float(__shfl_sync(FULL, ev0.y, t));
            int j1   = __shfl_sync(FULL, ev1.x, t);
            float v1 = __int_as_float(__shfl_sync(FULL, ev1.y, t));
            if (t < m0) {       // warp-uniform branch
                float4 a = xr[(size_t)j0 * 32 + lane];
                acc0.x += v0 * a.x; acc0.y += v0 * a.y;
                acc0.z += v0 * a.z; acc0.w += v0 * a.w;
            }
            if (t < m1) {
                float4 a = xr[(size_t)j1 * 32 + lane];
                acc1.x += v1 * a.x; acc1.y += v1 * a.y;
                acc1.z += v1 * a.z; acc1.w += v1 * a.w;
            }
        }
    }

    if (FUSE_LN) {
        acc0 = ln_epilogue<FUSE_LN, DO_LEAKY>(acc0, n0, lane, gamma, beta, res);
        acc1 = ln_epilogue<FUSE_LN, DO_LEAKY>(acc1, n1, lane, gamma, beta, res);
    }

    reinterpret_cast<float4*>(out + (size_t)n0 * HYPER_DIM)[lane] = acc0;
    reinterpret_cast<float4*>(out + (size_t)n1 * HYPER_DIM)[lane] = acc1;
}

// ---------------------------------------------------------------------------
// Launch: 5 kernels total.
// ---------------------------------------------------------------------------
extern "C" void kernel_launch(void* const* d_in, const int* in_sizes, int n_in,
                              void* d_out, int out_size) {
    const float* ego   = (const float*)d_in[0];
    const float* vals  = (const float*)d_in[1];
    const float* gamma = (const float*)d_in[2];   // [2, 128]
    const float* beta  = (const float*)d_in[3];   // [2, 128]
    const int*   rows  = (const int*)d_in[4];
    const int*   cols  = (const int*)d_in[5];
    float* out = (float*)d_out;

    float* ht; cudaGetSymbolAddress((void**)&ht, g_ht);
    float* em; cudaGetSymbolAddress((void**)&em, g_embs);
    int *cntA, *cntB; int2 *edgeA, *edgeB;
    cudaGetSymbolAddress((void**)&cntA, g_cntA);
    cudaGetSymbolAddress((void**)&cntB, g_cntB);
    cudaGetSymbolAddress((void**)&edgeA, g_edgeA);
    cudaGetSymbolAddress((void**)&edgeB, g_edgeB);

    // ---- bucket build (counters pre-zeroed by previous call / load) ----
    scatter_kernel<<<E4GRID, 256>>>((const int4*)rows, (const int4*)cols,
                                    (const float4*)vals);

    // ---- Layer 0 ----
    gather_spmm2_kernel<0, 0, 0><<<PGRID, 256>>>(cntA, edgeA, ego,
                                                 nullptr, nullptr, nullptr, ht);
    gather_spmm2_kernel<1, 1, 0><<<PGRID, 256>>>(cntB, edgeB, ht,
                                                 gamma, beta, ego, em);

    // ---- Layer 1 ----
    gather_spmm2_kernel<0, 0, 0><<<PGRID, 256>>>(cntA, edgeA, em,
                                                 nullptr, nullptr, nullptr, ht);
    gather_spmm2_kernel<1, 0, 1><<<PGRID, 256>>>(cntB, edgeB, ht,
                                                 gamma + HYPER_DIM, beta + HYPER_DIM,
                                                 ego, out);
}